// round 2
// baseline (speedup 1.0000x reference)
#include <cuda_runtime.h>
#include <cuda_bf16.h>
#include <math.h>

// ---------------- constants ----------------
#define BATCH 8
#define SLEN 1024
#define EMB 768
#define NH 12
#define HD 64
#define MROWS (BATCH*SLEN)          // 8192

// ---------------- device scratch (no allocations allowed) ----------------
__device__ float g_Q[BATCH*NH*SLEN*HD];
__device__ float g_K[BATCH*NH*SLEN*HD];
__device__ float g_V[BATCH*NH*SLEN*HD];
__device__ float g_AO[MROWS*EMB];
__device__ float g_gate[BATCH*NH*SLEN];
__device__ unsigned char g_bucket[SLEN*SLEN];

// ---------------- bucket table ----------------
// bucket(q,k): rp = k-q; base = (rp>0)*16; a=|rp|;
//   a<8 -> +a ; else += 8 + v, where v = trunc(2*log2(a/8)), capped at 7.
// Exact integer thresholds for v: a>=12 ->1, >=16 ->2, >=23 ->3, >=32 ->4,
//   >=46 ->5, >=64 ->6, >=91 ->7.
__global__ __launch_bounds__(256) void bucket_kernel() {
    int k = blockIdx.x * 256 + threadIdx.x;
    int q = blockIdx.y;
    int rp = k - q;
    int bucket = (rp > 0) ? 16 : 0;
    int a = (rp < 0) ? -rp : rp;
    int add;
    if      (a < 8)  add = a;
    else if (a < 12) add = 8;
    else if (a < 16) add = 9;
    else if (a < 23) add = 10;
    else if (a < 32) add = 11;
    else if (a < 46) add = 12;
    else if (a < 64) add = 13;
    else if (a < 91) add = 14;
    else             add = 15;
    g_bucket[q * SLEN + k] = (unsigned char)(bucket + add);
}

// ---------------- gate kernel ----------------
// g = sigmoid((ql @ gru_W + gru_b).reshape(...,2,4).sum(-1))  -- linear, so
// pre-sum the 8 columns of gru_W into two 64-vectors.
__global__ __launch_bounds__(256) void gate_kernel(
    const float* __restrict__ query,
    const float* __restrict__ gW,     // [64,8]
    const float* __restrict__ gb,     // [8]
    const float* __restrict__ gc)     // [12] (1,H,1,1)
{
    __shared__ float sw0[64], sw1[64];
    int tid = threadIdx.x;
    if (tid < 64) {
        const float* w = gW + tid * 8;
        sw0[tid] = w[0] + w[1] + w[2] + w[3];
        sw1[tid] = w[4] + w[5] + w[6] + w[7];
    }
    __syncthreads();
    float b0 = gb[0] + gb[1] + gb[2] + gb[3];
    float b1 = gb[4] + gb[5] + gb[6] + gb[7];

    int idx = blockIdx.x * 256 + tid;          // (b*12+h)*1024 + s
    int s = idx & (SLEN - 1);
    int h = (idx >> 10) % NH;
    int b = idx / (NH * SLEN);
    const float* q = query + ((size_t)(b * SLEN + s)) * EMB + h * HD;
    float z0 = b0, z1 = b1;
#pragma unroll 8
    for (int d = 0; d < HD; d++) {
        float qv = __ldg(&q[d]);
        z0 += qv * sw0[d];
        z1 += qv * sw1[d];
    }
    float g0 = 1.0f / (1.0f + expf(-z0));
    float g1 = 1.0f / (1.0f + expf(-z1));
    float gate = g0 * (g1 * gc[h] - 1.0f) + 2.0f;
    g_gate[idx] = gate;
}

// ---------------- QKV projection GEMM ----------------
// C[8192,768] = X @ W + b ; z = blockIdx.z selects (Wq,Wk,Wv).
// Output written in [b,h,s,d] layout; Q scaled by 0.125.
__global__ __launch_bounds__(256) void gemm_qkv_kernel(
    const float* __restrict__ X,
    const float* __restrict__ Wq, const float* __restrict__ bq,
    const float* __restrict__ Wk, const float* __restrict__ bk,
    const float* __restrict__ Wv, const float* __restrict__ bv)
{
    __shared__ float As[16][128];
    __shared__ float Bs[16][128];
    int z = blockIdx.z;
    const float* W    = (z == 0) ? Wq : ((z == 1) ? Wk : Wv);
    const float* bias = (z == 0) ? bq : ((z == 1) ? bk : bv);
    float* Out        = (z == 0) ? g_Q : ((z == 1) ? g_K : g_V);
    float scale = (z == 0) ? 0.125f : 1.0f;

    int bm = blockIdx.y * 128, bn = blockIdx.x * 128;
    int tid = threadIdx.x;
    int tx = tid & 15, ty = tid >> 4;

    float acc[8][8] = {};
    for (int k0 = 0; k0 < EMB; k0 += 16) {
#pragma unroll
        for (int r = 0; r < 2; r++) {
            int idx = tid + r * 256;
            int arow = idx >> 2, akq = (idx & 3) * 4;
            float4 a = *(const float4*)&X[(size_t)(bm + arow) * EMB + k0 + akq];
            As[akq + 0][arow] = a.x; As[akq + 1][arow] = a.y;
            As[akq + 2][arow] = a.z; As[akq + 3][arow] = a.w;
            int brw = idx >> 5, bcq = (idx & 31) * 4;
            *(float4*)&Bs[brw][bcq] =
                *(const float4*)&W[(size_t)(k0 + brw) * EMB + bn + bcq];
        }
        __syncthreads();
#pragma unroll
        for (int kk = 0; kk < 16; kk++) {
            float a[8], b[8];
            *(float4*)&a[0] = *(const float4*)&As[kk][ty * 8];
            *(float4*)&a[4] = *(const float4*)&As[kk][ty * 8 + 4];
            *(float4*)&b[0] = *(const float4*)&Bs[kk][tx * 8];
            *(float4*)&b[4] = *(const float4*)&Bs[kk][tx * 8 + 4];
#pragma unroll
            for (int i = 0; i < 8; i++)
#pragma unroll
                for (int j = 0; j < 8; j++)
                    acc[i][j] += a[i] * b[j];
        }
        __syncthreads();
    }
    int hcol = bn + tx * 8;
    int hh = hcol >> 6;
    int d0 = hcol & 63;
    float bb[8];
#pragma unroll
    for (int j = 0; j < 8; j++) bb[j] = bias[hcol + j];
#pragma unroll
    for (int i = 0; i < 8; i++) {
        int row = bm + ty * 8 + i;
        int b = row >> 10, sI = row & (SLEN - 1);
        float* op = Out + ((size_t)(b * NH + hh) * SLEN + sI) * HD + d0;
        float4 v0, v1;
        v0.x = (acc[i][0] + bb[0]) * scale; v0.y = (acc[i][1] + bb[1]) * scale;
        v0.z = (acc[i][2] + bb[2]) * scale; v0.w = (acc[i][3] + bb[3]) * scale;
        v1.x = (acc[i][4] + bb[4]) * scale; v1.y = (acc[i][5] + bb[5]) * scale;
        v1.z = (acc[i][6] + bb[6]) * scale; v1.w = (acc[i][7] + bb[7]) * scale;
        *(float4*)&op[0] = v0;
        *(float4*)&op[4] = v1;
    }
}

// ---------------- output projection GEMM ----------------
__global__ __launch_bounds__(256) void gemm_out_kernel(
    const float* __restrict__ Wo, const float* __restrict__ bo,
    float* __restrict__ out)
{
    __shared__ float As[16][128];
    __shared__ float Bs[16][128];
    int bm = blockIdx.y * 128, bn = blockIdx.x * 128;
    int tid = threadIdx.x;
    int tx = tid & 15, ty = tid >> 4;

    float acc[8][8] = {};
    for (int k0 = 0; k0 < EMB; k0 += 16) {
#pragma unroll
        for (int r = 0; r < 2; r++) {
            int idx = tid + r * 256;
            int arow = idx >> 2, akq = (idx & 3) * 4;
            float4 a = *(const float4*)&g_AO[(size_t)(bm + arow) * EMB + k0 + akq];
            As[akq + 0][arow] = a.x; As[akq + 1][arow] = a.y;
            As[akq + 2][arow] = a.z; As[akq + 3][arow] = a.w;
            int brw = idx >> 5, bcq = (idx & 31) * 4;
            *(float4*)&Bs[brw][bcq] =
                *(const float4*)&Wo[(size_t)(k0 + brw) * EMB + bn + bcq];
        }
        __syncthreads();
#pragma unroll
        for (int kk = 0; kk < 16; kk++) {
            float a[8], b[8];
            *(float4*)&a[0] = *(const float4*)&As[kk][ty * 8];
            *(float4*)&a[4] = *(const float4*)&As[kk][ty * 8 + 4];
            *(float4*)&b[0] = *(const float4*)&Bs[kk][tx * 8];
            *(float4*)&b[4] = *(const float4*)&Bs[kk][tx * 8 + 4];
#pragma unroll
            for (int i = 0; i < 8; i++)
#pragma unroll
                for (int j = 0; j < 8; j++)
                    acc[i][j] += a[i] * b[j];
        }
        __syncthreads();
    }
    int col = bn + tx * 8;
    float bb[8];
#pragma unroll
    for (int j = 0; j < 8; j++) bb[j] = bo[col + j];
#pragma unroll
    for (int i = 0; i < 8; i++) {
        int row = bm + ty * 8 + i;
        float4 v0, v1;
        v0.x = acc[i][0] + bb[0]; v0.y = acc[i][1] + bb[1];
        v0.z = acc[i][2] + bb[2]; v0.w = acc[i][3] + bb[3];
        v1.x = acc[i][4] + bb[4]; v1.y = acc[i][5] + bb[5];
        v1.z = acc[i][6] + bb[6]; v1.w = acc[i][7] + bb[7];
        *(float4*)&out[(size_t)row * EMB + col]     = v0;
        *(float4*)&out[(size_t)row * EMB + col + 4] = v1;
    }
}

// ---------------- flash attention ----------------
// grid: (96 = b*h, 16 = q tiles of 64). 256 threads, 4x4 microtiles.
// All smem tiles row-major with ld=68 floats (16B-aligned, 2-way worst case).
#define AT_LD 68
#define ATTN_SMEM_BYTES ((4*64*AT_LD + 64 + 32) * 4)

__global__ __launch_bounds__(256) void attn_kernel(const float* __restrict__ rel_embed)
{
    extern __shared__ float sm[];
    float* Qs = sm;                  // [64][68]
    float* Ks = Qs + 64 * AT_LD;     // [64][68]
    float* Vs = Ks + 64 * AT_LD;     // [64][68]
    float* Ps = Vs + 64 * AT_LD;     // [64][68]
    float* gate_s = Ps + 64 * AT_LD; // [64]
    float* relw   = gate_s + 64;     // [32]

    int bh = blockIdx.x;             // b*12 + h
    int qb = blockIdx.y;
    int h  = bh % NH;
    int tid = threadIdx.x;
    int tx = tid & 15, ty = tid >> 4;

    const float* Qg = g_Q + (size_t)(bh * SLEN + qb * 64) * HD;
    const float* Kg = g_K + (size_t)bh * SLEN * HD;
    const float* Vg = g_V + (size_t)bh * SLEN * HD;

#pragma unroll
    for (int r = 0; r < 4; r++) {
        int idx = tid + r * 256;
        int row = idx >> 4, dq = (idx & 15) * 4;
        *(float4*)&Qs[row * AT_LD + dq] = *(const float4*)&Qg[row * HD + dq];
    }
    if (tid < 64) gate_s[tid] = g_gate[bh * SLEN + qb * 64 + tid];
    if (tid < 32) relw[tid] = rel_embed[tid * NH + h];

    float m[4], l[4], o[4][4];
#pragma unroll
    for (int i = 0; i < 4; i++) {
        m[i] = -1e30f; l[i] = 0.0f;
#pragma unroll
        for (int j = 0; j < 4; j++) o[i][j] = 0.0f;
    }

    const unsigned char* brow = g_bucket + (size_t)(qb * 64) * SLEN;

    for (int kb = 0; kb < 16; kb++) {
        __syncthreads();   // prev PV reads done / Qs+gate visible on iter 0
#pragma unroll
        for (int r = 0; r < 4; r++) {
            int idx = tid + r * 256;
            int row = idx >> 4, dq = (idx & 15) * 4;
            *(float4*)&Ks[row * AT_LD + dq] =
                *(const float4*)&Kg[(kb * 64 + row) * HD + dq];
            *(float4*)&Vs[row * AT_LD + dq] =
                *(const float4*)&Vg[(kb * 64 + row) * HD + dq];
        }
        __syncthreads();

        // ---- scores: S = Q K^T (scale already in Q) ----
        float s[4][4] = {};
#pragma unroll 8
        for (int kk = 0; kk < HD; kk += 4) {
            float4 a[4], b[4];
#pragma unroll
            for (int i = 0; i < 4; i++)
                a[i] = *(const float4*)&Qs[(ty * 4 + i) * AT_LD + kk];
#pragma unroll
            for (int j = 0; j < 4; j++)
                b[j] = *(const float4*)&Ks[(tx * 4 + j) * AT_LD + kk];
#pragma unroll
            for (int i = 0; i < 4; i++)
#pragma unroll
                for (int j = 0; j < 4; j++)
                    s[i][j] += a[i].x * b[j].x + a[i].y * b[j].y +
                               a[i].z * b[j].z + a[i].w * b[j].w;
        }

        // ---- add gate * rel_pos_bias ----
        int kc0 = kb * 64 + tx * 4;
#pragma unroll
        for (int i = 0; i < 4; i++) {
            float g = gate_s[ty * 4 + i];
            const unsigned char* bp = brow + (size_t)(ty * 4 + i) * SLEN + kc0;
#pragma unroll
            for (int j = 0; j < 4; j++) s[i][j] += g * relw[bp[j]];
        }

        // ---- online softmax (16-lane row groups) ----
#pragma unroll
        for (int i = 0; i < 4; i++) {
            float tmax = fmaxf(fmaxf(s[i][0], s[i][1]), fmaxf(s[i][2], s[i][3]));
#pragma unroll
            for (int w = 1; w < 16; w <<= 1)
                tmax = fmaxf(tmax, __shfl_xor_sync(0xffffffffu, tmax, w));
            float mnew  = fmaxf(m[i], tmax);
            float alpha = __expf(m[i] - mnew);
            float rs = 0.0f;
#pragma unroll
            for (int j = 0; j < 4; j++) {
                s[i][j] = __expf(s[i][j] - mnew);
                rs += s[i][j];
            }
#pragma unroll
            for (int w = 1; w < 16; w <<= 1)
                rs += __shfl_xor_sync(0xffffffffu, rs, w);
            l[i] = l[i] * alpha + rs;
            m[i] = mnew;
#pragma unroll
            for (int j = 0; j < 4; j++) o[i][j] *= alpha;
        }

        // ---- P to smem ----
#pragma unroll
        for (int i = 0; i < 4; i++) {
            float4 pv = make_float4(s[i][0], s[i][1], s[i][2], s[i][3]);
            *(float4*)&Ps[(ty * 4 + i) * AT_LD + tx * 4] = pv;
        }
        __syncthreads();

        // ---- O += P V ----
#pragma unroll 4
        for (int kc = 0; kc < 64; kc += 4) {
            float4 a[4];
#pragma unroll
            for (int i = 0; i < 4; i++)
                a[i] = *(const float4*)&Ps[(ty * 4 + i) * AT_LD + kc];
#pragma unroll
            for (int t = 0; t < 4; t++) {
                float4 bv = *(const float4*)&Vs[(kc + t) * AT_LD + tx * 4];
#pragma unroll
                for (int i = 0; i < 4; i++) {
                    float av = ((const float*)&a[i])[t];
                    o[i][0] += av * bv.x;
                    o[i][1] += av * bv.y;
                    o[i][2] += av * bv.z;
                    o[i][3] += av * bv.w;
                }
            }
        }
    }

    // ---- epilogue: write [b, s, h*64+d] for the output projection ----
    int b = bh / NH;
#pragma unroll
    for (int i = 0; i < 4; i++) {
        float inv = 1.0f / l[i];
        float4 v = make_float4(o[i][0] * inv, o[i][1] * inv,
                               o[i][2] * inv, o[i][3] * inv);
        int row = qb * 64 + ty * 4 + i;
        *(float4*)&g_AO[(size_t)(b * SLEN + row) * EMB + h * HD + tx * 4] = v;
    }
}

// ---------------- launcher ----------------
extern "C" void kernel_launch(void* const* d_in, const int* in_sizes, int n_in,
                              void* d_out, int out_size)
{
    const float* query = (const float*)d_in[0];
    const float* Wq    = (const float*)d_in[1];
    const float* bq    = (const float*)d_in[2];
    const float* Wk    = (const float*)d_in[3];
    const float* bk    = (const float*)d_in[4];
    const float* Wv    = (const float*)d_in[5];
    const float* bv    = (const float*)d_in[6];
    const float* Wo    = (const float*)d_in[7];
    const float* bo    = (const float*)d_in[8];
    const float* rel   = (const float*)d_in[9];
    const float* gruW  = (const float*)d_in[10];
    const float* grub  = (const float*)d_in[11];
    const float* gruc  = (const float*)d_in[12];

    cudaFuncSetAttribute(attn_kernel,
                         cudaFuncAttributeMaxDynamicSharedMemorySize,
                         ATTN_SMEM_BYTES);

    bucket_kernel<<<dim3(4, SLEN), 256>>>();
    gate_kernel<<<BATCH * NH * SLEN / 256, 256>>>(query, gruW, grub, gruc);
    gemm_qkv_kernel<<<dim3(EMB / 128, MROWS / 128, 3), 256>>>(
        query, Wq, bq, Wk, bk, Wv, bv);
    attn_kernel<<<dim3(BATCH * NH, SLEN / 64), 256, ATTN_SMEM_BYTES>>>(rel);
    gemm_out_kernel<<<dim3(EMB / 128, MROWS / 128), 256>>>(
        Wo, bo, (float*)d_out);
}

// round 4
// speedup vs baseline: 1.7240x; 1.7240x over previous
#include <cuda_runtime.h>
#include <cuda_bf16.h>
#include <cstdint>
#include <math.h>

#define BATCH 8
#define SLEN 1024
#define EMB 768
#define NH 12
#define HD 64
#define MROWS (BATCH*SLEN)

__device__ float g_Q[BATCH*NH*SLEN*HD];
__device__ float g_K[BATCH*NH*SLEN*HD];
__device__ float g_V[BATCH*NH*SLEN*HD];
__device__ float g_gate[BATCH*NH*SLEN];
__device__ unsigned char g_bucket[SLEN*SLEN];
__device__ __nv_bfloat16 g_Xh[MROWS*EMB], g_Xl[MROWS*EMB];
__device__ __nv_bfloat16 g_AOh[MROWS*EMB], g_AOl[MROWS*EMB];
__device__ __nv_bfloat16 g_WTh[4*EMB*EMB], g_WTl[4*EMB*EMB];   // W^T [n][k]

__device__ __forceinline__ uint32_t smem_u32(const void* p) {
    uint32_t a;
    asm("{.reg .u64 t; cvta.to.shared.u64 t,%1; cvt.u32.u64 %0,t;}" : "=r"(a) : "l"(p));
    return a;
}
__device__ __forceinline__ void ldm4(uint32_t& r0, uint32_t& r1, uint32_t& r2,
                                     uint32_t& r3, uint32_t addr) {
    asm volatile("ldmatrix.sync.aligned.m8n8.x4.shared.b16 {%0,%1,%2,%3}, [%4];"
        : "=r"(r0),"=r"(r1),"=r"(r2),"=r"(r3) : "r"(addr));
}
__device__ __forceinline__ void mma16816(float* c, const uint32_t* a, const uint32_t* b) {
    asm volatile("mma.sync.aligned.m16n8k16.row.col.f32.bf16.bf16.f32 "
        "{%0,%1,%2,%3}, {%4,%5,%6,%7}, {%8,%9}, {%0,%1,%2,%3};"
        : "+f"(c[0]),"+f"(c[1]),"+f"(c[2]),"+f"(c[3])
        : "r"(a[0]),"r"(a[1]),"r"(a[2]),"r"(a[3]), "r"(b[0]),"r"(b[1]));
}

// ---- bucket ----
__global__ __launch_bounds__(256) void bucket_kernel() {
    int k = blockIdx.x*256 + threadIdx.x, q = blockIdx.y;
    int rp = k - q, base = (rp>0)?16:0, a = abs(rp), add;
    if(a<8)add=a; else if(a<12)add=8; else if(a<16)add=9; else if(a<23)add=10;
    else if(a<32)add=11; else if(a<46)add=12; else if(a<64)add=13; else if(a<91)add=14; else add=15;
    g_bucket[q*SLEN+k] = (unsigned char)(base+add);
}

// ---- gate ----
__global__ __launch_bounds__(256) void gate_kernel(
    const float* __restrict__ query, const float* __restrict__ gW,
    const float* __restrict__ gb, const float* __restrict__ gc)
{
    __shared__ float sw0[64], sw1[64];
    int tid = threadIdx.x;
    if (tid < 64) {
        const float* w = gW + tid*8;
        sw0[tid] = w[0]+w[1]+w[2]+w[3];
        sw1[tid] = w[4]+w[5]+w[6]+w[7];
    }
    __syncthreads();
    float b0 = gb[0]+gb[1]+gb[2]+gb[3], b1 = gb[4]+gb[5]+gb[6]+gb[7];
    int idx = blockIdx.x*256 + tid;
    int s = idx & (SLEN-1), h = (idx>>10)%NH, b = idx/(NH*SLEN);
    const float* q = query + ((size_t)(b*SLEN+s))*EMB + h*HD;
    float z0 = b0, z1 = b1;
#pragma unroll 8
    for (int d = 0; d < HD; d++) { float v = __ldg(&q[d]); z0 += v*sw0[d]; z1 += v*sw1[d]; }
    float g0 = 1.f/(1.f+expf(-z0)), g1 = 1.f/(1.f+expf(-z1));
    g_gate[idx] = g0*(g1*gc[h]-1.f)+2.f;
}

// ---- prep: split X ----
__global__ __launch_bounds__(256) void split_x_kernel(const float* __restrict__ x) {
    size_t i = ((size_t)blockIdx.x*256 + threadIdx.x)*4;
    float4 v = *(const float4*)(x+i);
    float vv[4] = {v.x,v.y,v.z,v.w};
#pragma unroll
    for (int j = 0; j < 4; j++) {
        __nv_bfloat16 h = __float2bfloat16(vv[j]);
        g_Xh[i+j] = h;
        g_Xl[i+j] = __float2bfloat16(vv[j] - __bfloat162float(h));
    }
}

// ---- prep: transpose + split W ----
__global__ __launch_bounds__(256) void trans_w_kernel(
    const float* __restrict__ wq, const float* __restrict__ wk,
    const float* __restrict__ wv, const float* __restrict__ wo)
{
    __shared__ float t[32][33];
    int z = blockIdx.z;
    const float* W = (z==0)?wq:(z==1)?wk:(z==2)?wv:wo;
    int tx = threadIdx.x & 31, ty = threadIdx.x >> 5;
    int n0 = blockIdx.x*32, k0 = blockIdx.y*32;
#pragma unroll
    for (int r = 0; r < 4; r++)
        t[ty+r*8][tx] = W[(size_t)(k0+ty+r*8)*EMB + n0+tx];
    __syncthreads();
#pragma unroll
    for (int r = 0; r < 4; r++) {
        float v = t[tx][ty+r*8];
        __nv_bfloat16 h = __float2bfloat16(v);
        size_t o = (size_t)z*EMB*EMB + (size_t)(n0+ty+r*8)*EMB + k0+tx;
        g_WTh[o] = h;
        g_WTl[o] = __float2bfloat16(v - __bfloat162float(h));
    }
}

// ==== mma.sync GEMM core ====
// C[128,128] per block, 8 warps (4 M x 2 N), warp tile 32x64.
// Smem tiles: [128 rows][40 bf16] (80B pitch -> ldmatrix conflict-free).
#define PITCH 40
#define TBYTES (128*PITCH*2)

struct GemmSmem {
    __nv_bfloat16 ah[128*PITCH];
    __nv_bfloat16 al[128*PITCH];
    __nv_bfloat16 bh[128*PITCH];
    __nv_bfloat16 bl[128*PITCH];
};

__device__ __forceinline__ void ld_tile32(const __nv_bfloat16* __restrict__ g,
                                          int row0, int kc, __nv_bfloat16* s, int tid) {
#pragma unroll
    for (int r = 0; r < 2; r++) {
        int u = tid + r*256;
        int row = u >> 2, sk = (u & 3) * 8;
        uint4 v = *(const uint4*)(g + (size_t)(row0+row)*EMB + kc + sk);
        *(uint4*)(s + row*PITCH + sk) = v;
    }
}

// accumulate c[2][8][4] over K=768
__device__ __forceinline__ void gemm_core(
    const __nv_bfloat16* Ah, const __nv_bfloat16* Al,
    const __nv_bfloat16* Bh, const __nv_bfloat16* Bl,
    int bm, int bn, GemmSmem* sm, float c[2][8][4])
{
    int tid = threadIdx.x, lane = tid & 31, wid = tid >> 5;
    int wm = wid & 3, wn = wid >> 2;
    // ldmatrix per-lane byte offsets
    uint32_t aoff = (((lane>>3)&1)*8 + (lane&7)) * (PITCH*2) + (lane>>4)*16;
    uint32_t boff = ((lane>>4)*8 + (lane&7)) * (PITCH*2) + ((lane>>3)&1)*16;
    uint32_t sAh = smem_u32(sm->ah), sAl = smem_u32(sm->al);
    uint32_t sBh = smem_u32(sm->bh), sBl = smem_u32(sm->bl);
    uint32_t aBaseH = sAh + (wm*32)*(PITCH*2) + aoff;
    uint32_t aBaseL = sAl + (wm*32)*(PITCH*2) + aoff;
    uint32_t bBaseH = sBh + (wn*64)*(PITCH*2) + boff;
    uint32_t bBaseL = sBl + (wn*64)*(PITCH*2) + boff;

    for (int kc = 0; kc < EMB; kc += 32) {
        ld_tile32(Ah, bm, kc, sm->ah, tid);
        ld_tile32(Al, bm, kc, sm->al, tid);
        ld_tile32(Bh, bn, kc, sm->bh, tid);
        ld_tile32(Bl, bn, kc, sm->bl, tid);
        __syncthreads();
#pragma unroll
        for (int ks = 0; ks < 32; ks += 16) {
            uint32_t ah[2][4], al[2][4], bhf[8][2], blf[8][2];
#pragma unroll
            for (int mi = 0; mi < 2; mi++) {
                ldm4(ah[mi][0],ah[mi][1],ah[mi][2],ah[mi][3],
                     aBaseH + mi*16*(PITCH*2) + ks*2);
                ldm4(al[mi][0],al[mi][1],al[mi][2],al[mi][3],
                     aBaseL + mi*16*(PITCH*2) + ks*2);
            }
#pragma unroll
            for (int jf = 0; jf < 4; jf++) {
                ldm4(bhf[jf*2][0],bhf[jf*2][1],bhf[jf*2+1][0],bhf[jf*2+1][1],
                     bBaseH + jf*16*(PITCH*2) + ks*2);
                ldm4(blf[jf*2][0],blf[jf*2][1],blf[jf*2+1][0],blf[jf*2+1][1],
                     bBaseL + jf*16*(PITCH*2) + ks*2);
            }
#pragma unroll
            for (int mi = 0; mi < 2; mi++)
#pragma unroll
                for (int nf = 0; nf < 8; nf++) {
                    mma16816(c[mi][nf], ah[mi], bhf[nf]);   // Ah*Bh
                    mma16816(c[mi][nf], ah[mi], blf[nf]);   // Ah*Bl
                    mma16816(c[mi][nf], al[mi], bhf[nf]);   // Al*Bh
                }
        }
        __syncthreads();
    }
}

// QKV: out to [b,h,s,d] fp32, Q scaled 0.125, bias added
__global__ __launch_bounds__(256) void gemm_qkv_mma(
    const float* __restrict__ bq, const float* __restrict__ bk, const float* __restrict__ bv)
{
    __shared__ GemmSmem sm;
    int z = blockIdx.z, bm = blockIdx.y*128, bn = blockIdx.x*128;
    float c[2][8][4] = {};
    gemm_core(g_Xh, g_Xl, g_WTh+(size_t)z*EMB*EMB, g_WTl+(size_t)z*EMB*EMB, bm, bn, &sm, c);

    const float* bias = (z==0)?bq:(z==1)?bk:bv;
    float* Out = (z==0)?g_Q:(z==1)?g_K:g_V;
    float scale = (z==0)?0.125f:1.f;
    int lane = threadIdx.x & 31, wid = threadIdx.x >> 5;
    int wm = wid & 3, wn = wid >> 2;
    int g = lane >> 2, cq = (lane & 3)*2;
#pragma unroll
    for (int mi = 0; mi < 2; mi++)
#pragma unroll
        for (int nf = 0; nf < 8; nf++) {
            int col = bn + wn*64 + nf*8 + cq;
            int h = col >> 6, d0 = col & 63;
            float bx = __ldg(&bias[col]), by = __ldg(&bias[col+1]);
#pragma unroll
            for (int rr = 0; rr < 2; rr++) {
                int m = bm + wm*32 + mi*16 + g + rr*8;
                int b = m >> 10, s = m & (SLEN-1);
                float2 v;
                v.x = (c[mi][nf][rr*2+0] + bx) * scale;
                v.y = (c[mi][nf][rr*2+1] + by) * scale;
                *(float2*)(Out + ((size_t)(b*NH+h)*SLEN + s)*HD + d0) = v;
            }
        }
}

// out projection: AO @ Wo + bo -> d_out [m][768]
__global__ __launch_bounds__(256) void gemm_out_mma(
    const float* __restrict__ bo, float* __restrict__ out)
{
    __shared__ GemmSmem sm;
    int bm = blockIdx.y*128, bn = blockIdx.x*128;
    float c[2][8][4] = {};
    gemm_core(g_AOh, g_AOl, g_WTh+(size_t)3*EMB*EMB, g_WTl+(size_t)3*EMB*EMB, bm, bn, &sm, c);

    int lane = threadIdx.x & 31, wid = threadIdx.x >> 5;
    int wm = wid & 3, wn = wid >> 2;
    int g = lane >> 2, cq = (lane & 3)*2;
#pragma unroll
    for (int mi = 0; mi < 2; mi++)
#pragma unroll
        for (int nf = 0; nf < 8; nf++) {
            int col = bn + wn*64 + nf*8 + cq;
            float bx = __ldg(&bo[col]), by = __ldg(&bo[col+1]);
#pragma unroll
            for (int rr = 0; rr < 2; rr++) {
                int m = bm + wm*32 + mi*16 + g + rr*8;
                float2 v;
                v.x = c[mi][nf][rr*2+0] + bx;
                v.y = c[mi][nf][rr*2+1] + by;
                *(float2*)(out + (size_t)m*EMB + col) = v;
            }
        }
}

// ==== flash attention: transposed Q/K smem ====
#define AT_LD 68
#define ATTN_SMEM ((4*64*AT_LD + 64 + 32)*4)

__device__ __forceinline__ void load_T(const float* __restrict__ g, float* dst, int tid) {
    int r = tid & 63, dg = (tid>>6)<<4;
#pragma unroll
    for (int t = 0; t < 4; t++) {
        float4 v = *(const float4*)&g[r*HD + dg + t*4];
        int d = dg + t*4;
        dst[(d+0)*AT_LD+r] = v.x; dst[(d+1)*AT_LD+r] = v.y;
        dst[(d+2)*AT_LD+r] = v.z; dst[(d+3)*AT_LD+r] = v.w;
    }
}

__global__ __launch_bounds__(256) void attn_kernel(const float* __restrict__ rel_embed)
{
    extern __shared__ float smf[];
    float* Qt = smf;
    float* Kt = Qt + 64*AT_LD;
    float* Vs = Kt + 64*AT_LD;
    float* Ps = Vs + 64*AT_LD;
    float* gate_s = Ps + 64*AT_LD;
    float* relw = gate_s + 64;

    int bh = blockIdx.x, qb = blockIdx.y, h = bh % NH;
    int tid = threadIdx.x, tx = tid & 15, ty = tid >> 4;
    const float* Qg = g_Q + (size_t)(bh*SLEN + qb*64)*HD;
    const float* Kg = g_K + (size_t)bh*SLEN*HD;
    const float* Vg = g_V + (size_t)bh*SLEN*HD;

    load_T(Qg, Qt, tid);
    if (tid < 64) gate_s[tid] = g_gate[bh*SLEN + qb*64 + tid];
    if (tid < 32) relw[tid] = rel_embed[tid*NH + h];

    float m[4], l[4], o[4][4];
#pragma unroll
    for (int i = 0; i < 4; i++) { m[i] = -1e30f; l[i] = 0.f;
#pragma unroll
        for (int j = 0; j < 4; j++) o[i][j] = 0.f; }

    const unsigned char* brow = g_bucket + (size_t)(qb*64)*SLEN;

    for (int kb = 0; kb < 16; kb++) {
        __syncthreads();
        load_T(Kg + (size_t)(kb*64)*HD, Kt, tid);
#pragma unroll
        for (int r = 0; r < 4; r++) {
            int idx = tid + r*256, row = idx>>4, dq = (idx&15)*4;
            *(float4*)&Vs[row*AT_LD+dq] = *(const float4*)&Vg[(kb*64+row)*HD+dq];
        }
        __syncthreads();

        float s[4][4] = {};
#pragma unroll 16
        for (int kk = 0; kk < HD; kk++) {
            float a[4], b[4];
            *(float4*)a = *(const float4*)&Qt[kk*AT_LD + ty*4];
            *(float4*)b = *(const float4*)&Kt[kk*AT_LD + tx*4];
#pragma unroll
            for (int i = 0; i < 4; i++)
#pragma unroll
                for (int j = 0; j < 4; j++) s[i][j] += a[i]*b[j];
        }

        int kc0 = kb*64 + tx*4;
#pragma unroll
        for (int i = 0; i < 4; i++) {
            float g = gate_s[ty*4+i];
            const unsigned char* bp = brow + (size_t)(ty*4+i)*SLEN + kc0;
#pragma unroll
            for (int j = 0; j < 4; j++) s[i][j] += g*relw[bp[j]];
        }

#pragma unroll
        for (int i = 0; i < 4; i++) {
            float tm = fmaxf(fmaxf(s[i][0],s[i][1]), fmaxf(s[i][2],s[i][3]));
#pragma unroll
            for (int w = 1; w < 16; w <<= 1) tm = fmaxf(tm, __shfl_xor_sync(~0u, tm, w));
            float mn = fmaxf(m[i], tm), al = __expf(m[i]-mn), rs = 0.f;
#pragma unroll
            for (int j = 0; j < 4; j++) { s[i][j] = __expf(s[i][j]-mn); rs += s[i][j]; }
#pragma unroll
            for (int w = 1; w < 16; w <<= 1) rs += __shfl_xor_sync(~0u, rs, w);
            l[i] = l[i]*al + rs; m[i] = mn;
#pragma unroll
            for (int j = 0; j < 4; j++) o[i][j] *= al;
        }

#pragma unroll
        for (int i = 0; i < 4; i++)
            *(float4*)&Ps[(ty*4+i)*AT_LD + tx*4] = make_float4(s[i][0],s[i][1],s[i][2],s[i][3]);
        __syncthreads();

#pragma unroll 4
        for (int kc = 0; kc < 64; kc += 4) {
            float4 a[4];
#pragma unroll
            for (int i = 0; i < 4; i++) a[i] = *(const float4*)&Ps[(ty*4+i)*AT_LD + kc];
#pragma unroll
            for (int t = 0; t < 4; t++) {
                float4 bv = *(const float4*)&Vs[(kc+t)*AT_LD + tx*4];
#pragma unroll
                for (int i = 0; i < 4; i++) {
                    float av = ((const float*)&a[i])[t];
                    o[i][0] += av*bv.x; o[i][1] += av*bv.y;
                    o[i][2] += av*bv.z; o[i][3] += av*bv.w;
                }
            }
        }
    }

    int b = bh / NH;
#pragma unroll
    for (int i = 0; i < 4; i++) {
        float inv = 1.f/l[i];
        int row = qb*64 + ty*4 + i;
        size_t base = (size_t)(b*SLEN+row)*EMB + h*HD + tx*4;
#pragma unroll
        for (int j = 0; j < 4; j++) {
            float v = o[i][j]*inv;
            __nv_bfloat16 hh = __float2bfloat16(v);
            g_AOh[base+j] = hh;
            g_AOl[base+j] = __float2bfloat16(v - __bfloat162float(hh));
        }
    }
}

// ---- launcher ----
extern "C" void kernel_launch(void* const* d_in, const int* in_sizes, int n_in,
                              void* d_out, int out_size)
{
    const float* query = (const float*)d_in[0];
    const float *Wq=(const float*)d_in[1], *bq=(const float*)d_in[2];
    const float *Wk=(const float*)d_in[3], *bk=(const float*)d_in[4];
    const float *Wv=(const float*)d_in[5], *bv=(const float*)d_in[6];
    const float *Wo=(const float*)d_in[7], *bo=(const float*)d_in[8];
    const float *rel=(const float*)d_in[9];
    const float *gruW=(const float*)d_in[10], *grub=(const float*)d_in[11], *gruc=(const float*)d_in[12];

    cudaFuncSetAttribute(attn_kernel, cudaFuncAttributeMaxDynamicSharedMemorySize, ATTN_SMEM);

    bucket_kernel<<<dim3(4, SLEN), 256>>>();
    gate_kernel<<<BATCH*NH*SLEN/256, 256>>>(query, gruW, grub, gruc);
    split_x_kernel<<<MROWS*EMB/1024, 256>>>(query);
    trans_w_kernel<<<dim3(EMB/32, EMB/32, 4), 256>>>(Wq, Wk, Wv, Wo);
    gemm_qkv_mma<<<dim3(EMB/128, MROWS/128, 3), 256>>>(bq, bk, bv);
    attn_kernel<<<dim3(BATCH*NH, SLEN/64), 256, ATTN_SMEM>>>(rel);
    gemm_out_mma<<<dim3(EMB/128, MROWS/128), 256>>>(bo, (float*)d_out);
}

// round 5
// speedup vs baseline: 2.3082x; 1.3389x over previous
#include <cuda_runtime.h>
#include <cuda_bf16.h>
#include <cstdint>
#include <math.h>

#define BATCH 8
#define SLEN 1024
#define EMB 768
#define NH 12
#define HD 64
#define MROWS (BATCH*SLEN)

__device__ float g_gate[BATCH*NH*SLEN];
__device__ unsigned char g_bucket[SLEN*SLEN];
__device__ __nv_bfloat16 g_Xh[MROWS*EMB], g_Xl[MROWS*EMB];
__device__ __nv_bfloat16 g_AOh[MROWS*EMB], g_AOl[MROWS*EMB];
__device__ __nv_bfloat16 g_WTh[4*EMB*EMB], g_WTl[4*EMB*EMB];
// Q/K/V bf16 hi/lo in [b,h,s,d]
__device__ __nv_bfloat16 g_Qh[BATCH*NH*SLEN*HD], g_Ql[BATCH*NH*SLEN*HD];
__device__ __nv_bfloat16 g_Kh[BATCH*NH*SLEN*HD], g_Kl[BATCH*NH*SLEN*HD];
__device__ __nv_bfloat16 g_Vh[BATCH*NH*SLEN*HD], g_Vl[BATCH*NH*SLEN*HD];

__device__ __forceinline__ uint32_t smem_u32(const void* p) {
    uint32_t a;
    asm("{.reg .u64 t; cvta.to.shared.u64 t,%1; cvt.u32.u64 %0,t;}" : "=r"(a) : "l"(p));
    return a;
}
__device__ __forceinline__ void ldm4(uint32_t* r, uint32_t addr) {
    asm volatile("ldmatrix.sync.aligned.m8n8.x4.shared.b16 {%0,%1,%2,%3}, [%4];"
        : "=r"(r[0]),"=r"(r[1]),"=r"(r[2]),"=r"(r[3]) : "r"(addr));
}
__device__ __forceinline__ void ldm4t(uint32_t* r, uint32_t addr) {
    asm volatile("ldmatrix.sync.aligned.m8n8.x4.trans.shared.b16 {%0,%1,%2,%3}, [%4];"
        : "=r"(r[0]),"=r"(r[1]),"=r"(r[2]),"=r"(r[3]) : "r"(addr));
}
__device__ __forceinline__ void mma16816(float* c, const uint32_t* a, const uint32_t* b) {
    asm volatile("mma.sync.aligned.m16n8k16.row.col.f32.bf16.bf16.f32 "
        "{%0,%1,%2,%3}, {%4,%5,%6,%7}, {%8,%9}, {%0,%1,%2,%3};"
        : "+f"(c[0]),"+f"(c[1]),"+f"(c[2]),"+f"(c[3])
        : "r"(a[0]),"r"(a[1]),"r"(a[2]),"r"(a[3]), "r"(b[0]),"r"(b[1]));
}
__device__ __forceinline__ uint32_t pack_bf16x2(float hi, float lo) {
    uint32_t r;
    asm("cvt.rn.bf16x2.f32 %0, %1, %2;" : "=r"(r) : "f"(hi), "f"(lo));
    return r;
}
// e^x for x<=0, FMA-pipe only (no MUFU). max rel err ~2.4e-6
__device__ __forceinline__ float fexp(float x) {
    float y = fmaxf(x * 1.4426950408889634f, -80.f);
    float t = y + 12582912.f;
    int  i = __float_as_int(t) << 23;
    float f = y - (t - 12582912.f);
    float p = 0.0013333558f;
    p = fmaf(p, f, 0.0096181291f);
    p = fmaf(p, f, 0.0555041087f);
    p = fmaf(p, f, 0.2402265069f);
    p = fmaf(p, f, 0.6931471806f);
    p = fmaf(p, f, 1.0f);
    return __int_as_float(__float_as_int(p) + i);
}

// ---- bucket ----
__global__ __launch_bounds__(256) void bucket_kernel() {
    int k = blockIdx.x*256 + threadIdx.x, q = blockIdx.y;
    int rp = k - q, base = (rp>0)?16:0, a = abs(rp), add;
    if(a<8)add=a; else if(a<12)add=8; else if(a<16)add=9; else if(a<23)add=10;
    else if(a<32)add=11; else if(a<46)add=12; else if(a<64)add=13; else if(a<91)add=14; else add=15;
    g_bucket[q*SLEN+k] = (unsigned char)(base+add);
}

// ---- gate ----
__global__ __launch_bounds__(256) void gate_kernel(
    const float* __restrict__ query, const float* __restrict__ gW,
    const float* __restrict__ gb, const float* __restrict__ gc)
{
    __shared__ float sw0[64], sw1[64];
    int tid = threadIdx.x;
    if (tid < 64) {
        const float* w = gW + tid*8;
        sw0[tid] = w[0]+w[1]+w[2]+w[3];
        sw1[tid] = w[4]+w[5]+w[6]+w[7];
    }
    __syncthreads();
    float b0 = gb[0]+gb[1]+gb[2]+gb[3], b1 = gb[4]+gb[5]+gb[6]+gb[7];
    int idx = blockIdx.x*256 + tid;
    int s = idx & (SLEN-1), h = (idx>>10)%NH, b = idx/(NH*SLEN);
    const float* q = query + ((size_t)(b*SLEN+s))*EMB + h*HD;
    float z0 = b0, z1 = b1;
#pragma unroll 8
    for (int d = 0; d < HD; d++) { float v = __ldg(&q[d]); z0 += v*sw0[d]; z1 += v*sw1[d]; }
    float g0 = 1.f/(1.f+expf(-z0)), g1 = 1.f/(1.f+expf(-z1));
    g_gate[idx] = g0*(g1*gc[h]-1.f)+2.f;
}

// ---- prep: split X ----
__global__ __launch_bounds__(256) void split_x_kernel(const float* __restrict__ x) {
    size_t i = ((size_t)blockIdx.x*256 + threadIdx.x)*4;
    float4 v = *(const float4*)(x+i);
    float vv[4] = {v.x,v.y,v.z,v.w};
#pragma unroll
    for (int j = 0; j < 4; j++) {
        __nv_bfloat16 h = __float2bfloat16(vv[j]);
        g_Xh[i+j] = h;
        g_Xl[i+j] = __float2bfloat16(vv[j] - __bfloat162float(h));
    }
}

// ---- prep: transpose + split W ----
__global__ __launch_bounds__(256) void trans_w_kernel(
    const float* __restrict__ wq, const float* __restrict__ wk,
    const float* __restrict__ wv, const float* __restrict__ wo)
{
    __shared__ float t[32][33];
    int z = blockIdx.z;
    const float* W = (z==0)?wq:(z==1)?wk:(z==2)?wv:wo;
    int tx = threadIdx.x & 31, ty = threadIdx.x >> 5;
    int n0 = blockIdx.x*32, k0 = blockIdx.y*32;
#pragma unroll
    for (int r = 0; r < 4; r++)
        t[ty+r*8][tx] = W[(size_t)(k0+ty+r*8)*EMB + n0+tx];
    __syncthreads();
#pragma unroll
    for (int r = 0; r < 4; r++) {
        float v = t[tx][ty+r*8];
        __nv_bfloat16 h = __float2bfloat16(v);
        size_t o = (size_t)z*EMB*EMB + (size_t)(n0+ty+r*8)*EMB + k0+tx;
        g_WTh[o] = h;
        g_WTl[o] = __float2bfloat16(v - __bfloat162float(h));
    }
}

// ==== mma.sync GEMM core (as R4) ====
#define PITCH 40
struct GemmSmem {
    __nv_bfloat16 ah[128*PITCH];
    __nv_bfloat16 al[128*PITCH];
    __nv_bfloat16 bh[128*PITCH];
    __nv_bfloat16 bl[128*PITCH];
};

__device__ __forceinline__ void ld_tile32(const __nv_bfloat16* __restrict__ g,
                                          int row0, int kc, __nv_bfloat16* s, int tid) {
#pragma unroll
    for (int r = 0; r < 2; r++) {
        int u = tid + r*256;
        int row = u >> 2, sk = (u & 3) * 8;
        uint4 v = *(const uint4*)(g + (size_t)(row0+row)*EMB + kc + sk);
        *(uint4*)(s + row*PITCH + sk) = v;
    }
}

__device__ __forceinline__ void gemm_core(
    const __nv_bfloat16* Ah, const __nv_bfloat16* Al,
    const __nv_bfloat16* Bh, const __nv_bfloat16* Bl,
    int bm, int bn, GemmSmem* sm, float c[2][8][4])
{
    int tid = threadIdx.x, lane = tid & 31, wid = tid >> 5;
    int wm = wid & 3, wn = wid >> 2;
    uint32_t aoff = (((lane>>3)&1)*8 + (lane&7)) * (PITCH*2) + (lane>>4)*16;
    uint32_t boff = ((lane>>4)*8 + (lane&7)) * (PITCH*2) + ((lane>>3)&1)*16;
    uint32_t aBaseH = smem_u32(sm->ah) + (wm*32)*(PITCH*2) + aoff;
    uint32_t aBaseL = smem_u32(sm->al) + (wm*32)*(PITCH*2) + aoff;
    uint32_t bBaseH = smem_u32(sm->bh) + (wn*64)*(PITCH*2) + boff;
    uint32_t bBaseL = smem_u32(sm->bl) + (wn*64)*(PITCH*2) + boff;

    for (int kc = 0; kc < EMB; kc += 32) {
        ld_tile32(Ah, bm, kc, sm->ah, tid);
        ld_tile32(Al, bm, kc, sm->al, tid);
        ld_tile32(Bh, bn, kc, sm->bh, tid);
        ld_tile32(Bl, bn, kc, sm->bl, tid);
        __syncthreads();
#pragma unroll
        for (int ks = 0; ks < 32; ks += 16) {
            uint32_t ah[2][4], al[2][4], bhf[8][2], blf[8][2];
#pragma unroll
            for (int mi = 0; mi < 2; mi++) {
                ldm4(ah[mi], aBaseH + mi*16*(PITCH*2) + ks*2);
                ldm4(al[mi], aBaseL + mi*16*(PITCH*2) + ks*2);
            }
#pragma unroll
            for (int jf = 0; jf < 4; jf++) {
                uint32_t rh[4], rl[4];
                ldm4(rh, bBaseH + jf*16*(PITCH*2) + ks*2);
                ldm4(rl, bBaseL + jf*16*(PITCH*2) + ks*2);
                bhf[jf*2][0]=rh[0]; bhf[jf*2][1]=rh[1]; bhf[jf*2+1][0]=rh[2]; bhf[jf*2+1][1]=rh[3];
                blf[jf*2][0]=rl[0]; blf[jf*2][1]=rl[1]; blf[jf*2+1][0]=rl[2]; blf[jf*2+1][1]=rl[3];
            }
#pragma unroll
            for (int mi = 0; mi < 2; mi++)
#pragma unroll
                for (int nf = 0; nf < 8; nf++) {
                    mma16816(c[mi][nf], ah[mi], bhf[nf]);
                    mma16816(c[mi][nf], ah[mi], blf[nf]);
                    mma16816(c[mi][nf], al[mi], bhf[nf]);
                }
        }
        __syncthreads();
    }
}

// QKV projection -> bf16 hi/lo [b,h,s,d]; Q scaled 0.125
__global__ __launch_bounds__(256) void gemm_qkv_mma(
    const float* __restrict__ bq, const float* __restrict__ bk, const float* __restrict__ bv)
{
    __shared__ GemmSmem sm;
    int z = blockIdx.z, bm = blockIdx.y*128, bn = blockIdx.x*128;
    float c[2][8][4] = {};
    gemm_core(g_Xh, g_Xl, g_WTh+(size_t)z*EMB*EMB, g_WTl+(size_t)z*EMB*EMB, bm, bn, &sm, c);

    const float* bias = (z==0)?bq:(z==1)?bk:bv;
    __nv_bfloat16* Oh = (z==0)?g_Qh:(z==1)?g_Kh:g_Vh;
    __nv_bfloat16* Ol = (z==0)?g_Ql:(z==1)?g_Kl:g_Vl;
    float scale = (z==0)?0.125f:1.f;
    int lane = threadIdx.x & 31, wid = threadIdx.x >> 5;
    int wm = wid & 3, wn = wid >> 2;
    int g = lane >> 2, cq = (lane & 3)*2;
#pragma unroll
    for (int mi = 0; mi < 2; mi++)
#pragma unroll
        for (int nf = 0; nf < 8; nf++) {
            int col = bn + wn*64 + nf*8 + cq;
            int h = col >> 6, d0 = col & 63;
            float bx = __ldg(&bias[col]), by = __ldg(&bias[col+1]);
#pragma unroll
            for (int rr = 0; rr < 2; rr++) {
                int m = bm + wm*32 + mi*16 + g + rr*8;
                int b = m >> 10, s = m & (SLEN-1);
                float vx = (c[mi][nf][rr*2+0] + bx) * scale;
                float vy = (c[mi][nf][rr*2+1] + by) * scale;
                __nv_bfloat162 hv, lv;
                hv.x = __float2bfloat16(vx);
                hv.y = __float2bfloat16(vy);
                lv.x = __float2bfloat16(vx - __bfloat162float(hv.x));
                lv.y = __float2bfloat16(vy - __bfloat162float(hv.y));
                size_t off = ((size_t)(b*NH+h)*SLEN + s)*HD + d0;
                *(__nv_bfloat162*)(Oh + off) = hv;
                *(__nv_bfloat162*)(Ol + off) = lv;
            }
        }
}

// out projection (unchanged from R4)
__global__ __launch_bounds__(256) void gemm_out_mma(
    const float* __restrict__ bo, float* __restrict__ out)
{
    __shared__ GemmSmem sm;
    int bm = blockIdx.y*128, bn = blockIdx.x*128;
    float c[2][8][4] = {};
    gemm_core(g_AOh, g_AOl, g_WTh+(size_t)3*EMB*EMB, g_WTl+(size_t)3*EMB*EMB, bm, bn, &sm, c);

    int lane = threadIdx.x & 31, wid = threadIdx.x >> 5;
    int wm = wid & 3, wn = wid >> 2;
    int g = lane >> 2, cq = (lane & 3)*2;
#pragma unroll
    for (int mi = 0; mi < 2; mi++)
#pragma unroll
        for (int nf = 0; nf < 8; nf++) {
            int col = bn + wn*64 + nf*8 + cq;
            float bx = __ldg(&bo[col]), by = __ldg(&bo[col+1]);
#pragma unroll
            for (int rr = 0; rr < 2; rr++) {
                int m = bm + wm*32 + mi*16 + g + rr*8;
                float2 v;
                v.x = c[mi][nf][rr*2+0] + bx;
                v.y = c[mi][nf][rr*2+1] + by;
                *(float2*)(out + (size_t)m*EMB + col) = v;
            }
        }
}

// ==== tensor-core flash attention ====
// 128 threads (4 warps), q-tile 64. Warp w owns q-rows 16w..16w+15.
// smem tiles [64][72] bf16 (144B pitch, ldmatrix conflict-free).
#define AP 72
#define ATILE (64*AP*2)
#define AS_QH 0
#define AS_QL (ATILE)
#define AS_KH (2*ATILE)
#define AS_KL (3*ATILE)
#define AS_VH (4*ATILE)
#define AS_VL (5*ATILE)
#define AS_GATE (6*ATILE)
#define AS_RELW (6*ATILE + 256)
#define AS_TOTAL (6*ATILE + 256 + 128)

__global__ __launch_bounds__(128) void attn_mma(const float* __restrict__ rel_embed)
{
    extern __shared__ char smc[];
    __nv_bfloat16* qhs = (__nv_bfloat16*)(smc + AS_QH);
    __nv_bfloat16* qls = (__nv_bfloat16*)(smc + AS_QL);
    __nv_bfloat16* khs = (__nv_bfloat16*)(smc + AS_KH);
    __nv_bfloat16* kls = (__nv_bfloat16*)(smc + AS_KL);
    __nv_bfloat16* vhs = (__nv_bfloat16*)(smc + AS_VH);
    __nv_bfloat16* vls = (__nv_bfloat16*)(smc + AS_VL);
    float* gate_s = (float*)(smc + AS_GATE);
    float* relw   = (float*)(smc + AS_RELW);

    int bh = blockIdx.x, qb = blockIdx.y, h = bh % NH;
    int tid = threadIdx.x, lane = tid & 31, w = tid >> 5;
    int g = lane >> 2, t2 = (lane & 3) * 2;

    // load Q tiles + gate + relw
    const __nv_bfloat16* Qhg = g_Qh + ((size_t)bh*SLEN + qb*64)*HD;
    const __nv_bfloat16* Qlg = g_Ql + ((size_t)bh*SLEN + qb*64)*HD;
#pragma unroll
    for (int r = 0; r < 4; r++) {
        int u = tid + r*128, row = u >> 3, c8 = (u & 7) * 8;
        *(uint4*)(qhs + row*AP + c8) = *(const uint4*)(Qhg + row*HD + c8);
        *(uint4*)(qls + row*AP + c8) = *(const uint4*)(Qlg + row*HD + c8);
    }
    if (tid < 64) gate_s[tid] = g_gate[bh*SLEN + qb*64 + tid];
    if (tid < 32) relw[tid] = rel_embed[tid*NH + h];
    __syncthreads();

    uint32_t aoff = (((lane>>3)&1)*8 + (lane&7)) * (AP*2) + (lane>>4)*16;
    uint32_t boff = ((lane>>4)*8 + (lane&7)) * (AP*2) + ((lane>>3)&1)*16;
    uint32_t qhB = smem_u32(qhs) + w*16*(AP*2) + aoff;
    uint32_t qlB = smem_u32(qls) + w*16*(AP*2) + aoff;
    uint32_t khB = smem_u32(khs) + boff;
    uint32_t klB = smem_u32(kls) + boff;
    uint32_t vhB = smem_u32(vhs) + aoff;
    uint32_t vlB = smem_u32(vls) + aoff;

    // Q fragments (constant across k-tiles)
    uint32_t qfh[4][4], qfl[4][4];
#pragma unroll
    for (int ks = 0; ks < 4; ks++) {
        ldm4(qfh[ks], qhB + ks*32);
        ldm4(qfl[ks], qlB + ks*32);
    }
    float gq0 = gate_s[w*16 + g], gq1 = gate_s[w*16 + g + 8];
    int q0 = qb*64 + w*16 + g;
    const unsigned char* br0 = g_bucket + (size_t)q0*SLEN;
    const unsigned char* br1 = br0 + 8*SLEN;

    float o[8][4] = {};
    float m0 = -1e30f, m1 = -1e30f, l0 = 0.f, l1 = 0.f;

    const __nv_bfloat16* Khg = g_Kh + (size_t)bh*SLEN*HD;
    const __nv_bfloat16* Klg = g_Kl + (size_t)bh*SLEN*HD;
    const __nv_bfloat16* Vhg = g_Vh + (size_t)bh*SLEN*HD;
    const __nv_bfloat16* Vlg = g_Vl + (size_t)bh*SLEN*HD;

    for (int kb = 0; kb < 16; kb++) {
        __syncthreads();
#pragma unroll
        for (int r = 0; r < 4; r++) {
            int u = tid + r*128, row = u >> 3, c8 = (u & 7) * 8;
            size_t go = (size_t)(kb*64 + row)*HD + c8;
            *(uint4*)(khs + row*AP + c8) = *(const uint4*)(Khg + go);
            *(uint4*)(kls + row*AP + c8) = *(const uint4*)(Klg + go);
            *(uint4*)(vhs + row*AP + c8) = *(const uint4*)(Vhg + go);
            *(uint4*)(vls + row*AP + c8) = *(const uint4*)(Vlg + go);
        }
        __syncthreads();

        // ---- S = Q K^T (3-split) ----
        float s[8][4] = {};
#pragma unroll
        for (int ks = 0; ks < 4; ks++)
#pragma unroll
            for (int nb = 0; nb < 4; nb++) {
                uint32_t rh[4], rl[4];
                ldm4(rh, khB + nb*16*(AP*2) + ks*32);
                ldm4(rl, klB + nb*16*(AP*2) + ks*32);
                mma16816(s[nb*2],   qfh[ks], rh);   mma16816(s[nb*2],   qfh[ks], rl);
                mma16816(s[nb*2],   qfl[ks], rh);
                mma16816(s[nb*2+1], qfh[ks], rh+2); mma16816(s[nb*2+1], qfh[ks], rl+2);
                mma16816(s[nb*2+1], qfl[ks], rh+2);
            }

        // ---- bias: gate * rel_pos ----
        int c0 = kb*64 + t2;
#pragma unroll
        for (int nf = 0; nf < 8; nf++) {
            int cc = c0 + nf*8;
            s[nf][0] += gq0 * relw[__ldg(&br0[cc])];
            s[nf][1] += gq0 * relw[__ldg(&br0[cc+1])];
            s[nf][2] += gq1 * relw[__ldg(&br1[cc])];
            s[nf][3] += gq1 * relw[__ldg(&br1[cc+1])];
        }

        // ---- online softmax ----
        float mx0 = -1e30f, mx1 = -1e30f;
#pragma unroll
        for (int nf = 0; nf < 8; nf++) {
            mx0 = fmaxf(mx0, fmaxf(s[nf][0], s[nf][1]));
            mx1 = fmaxf(mx1, fmaxf(s[nf][2], s[nf][3]));
        }
        mx0 = fmaxf(mx0, __shfl_xor_sync(~0u, mx0, 1));
        mx0 = fmaxf(mx0, __shfl_xor_sync(~0u, mx0, 2));
        mx1 = fmaxf(mx1, __shfl_xor_sync(~0u, mx1, 1));
        mx1 = fmaxf(mx1, __shfl_xor_sync(~0u, mx1, 2));
        float mn0 = fmaxf(m0, mx0), mn1 = fmaxf(m1, mx1);
        float a0 = fexp(m0 - mn0), a1 = fexp(m1 - mn1);
        float rs0 = 0.f, rs1 = 0.f;
#pragma unroll
        for (int nf = 0; nf < 8; nf++) {
            s[nf][0] = fexp(s[nf][0] - mn0); rs0 += s[nf][0];
            s[nf][1] = fexp(s[nf][1] - mn0); rs0 += s[nf][1];
            s[nf][2] = fexp(s[nf][2] - mn1); rs1 += s[nf][2];
            s[nf][3] = fexp(s[nf][3] - mn1); rs1 += s[nf][3];
        }
        rs0 += __shfl_xor_sync(~0u, rs0, 1); rs0 += __shfl_xor_sync(~0u, rs0, 2);
        rs1 += __shfl_xor_sync(~0u, rs1, 1); rs1 += __shfl_xor_sync(~0u, rs1, 2);
        l0 = l0*a0 + rs0; l1 = l1*a1 + rs1; m0 = mn0; m1 = mn1;
#pragma unroll
        for (int nf = 0; nf < 8; nf++) {
            o[nf][0] *= a0; o[nf][1] *= a0; o[nf][2] *= a1; o[nf][3] *= a1;
        }

        // ---- O += P V (3-split, P packed in-register) ----
#pragma unroll
        for (int ks = 0; ks < 4; ks++) {
            float* p0 = s[2*ks];
            float* p1 = s[2*ks+1];
            uint32_t pah[4], pal[4];
            pah[0] = pack_bf16x2(p0[1], p0[0]);
            pah[1] = pack_bf16x2(p0[3], p0[2]);
            pah[2] = pack_bf16x2(p1[1], p1[0]);
            pah[3] = pack_bf16x2(p1[3], p1[2]);
            pal[0] = pack_bf16x2(p0[1] - __int_as_float(pah[0] & 0xFFFF0000u),
                                 p0[0] - __int_as_float(pah[0] << 16));
            pal[1] = pack_bf16x2(p0[3] - __int_as_float(pah[1] & 0xFFFF0000u),
                                 p0[2] - __int_as_float(pah[1] << 16));
            pal[2] = pack_bf16x2(p1[1] - __int_as_float(pah[2] & 0xFFFF0000u),
                                 p1[0] - __int_as_float(pah[2] << 16));
            pal[3] = pack_bf16x2(p1[3] - __int_as_float(pah[3] & 0xFFFF0000u),
                                 p1[2] - __int_as_float(pah[3] << 16));
#pragma unroll
            for (int db = 0; db < 4; db++) {
                uint32_t rh[4], rl[4];
                ldm4t(rh, vhB + ks*16*(AP*2) + db*32);
                ldm4t(rl, vlB + ks*16*(AP*2) + db*32);
                mma16816(o[db*2],   pah, rh);   mma16816(o[db*2],   pah, rl);
                mma16816(o[db*2],   pal, rh);
                mma16816(o[db*2+1], pah, rh+2); mma16816(o[db*2+1], pah, rl+2);
                mma16816(o[db*2+1], pal, rh+2);
            }
        }
    }

    // ---- epilogue: O/l -> bf16 hi/lo AO at [b, s, h*64+d] ----
    float inv0 = 1.f/l0, inv1 = 1.f/l1;
    int b = bh / NH;
    size_t base0 = ((size_t)(b*SLEN) + q0)*EMB + h*HD;
    size_t base1 = base0 + (size_t)8*EMB;
#pragma unroll
    for (int nf = 0; nf < 8; nf++) {
        int d = nf*8 + t2;
        float v0 = o[nf][0]*inv0, v1 = o[nf][1]*inv0;
        float v2 = o[nf][2]*inv1, v3 = o[nf][3]*inv1;
        __nv_bfloat162 hv, lv;
        hv.x = __float2bfloat16(v0); hv.y = __float2bfloat16(v1);
        lv.x = __float2bfloat16(v0 - __bfloat162float(hv.x));
        lv.y = __float2bfloat16(v1 - __bfloat162float(hv.y));
        *(__nv_bfloat162*)(g_AOh + base0 + d) = hv;
        *(__nv_bfloat162*)(g_AOl + base0 + d) = lv;
        hv.x = __float2bfloat16(v2); hv.y = __float2bfloat16(v3);
        lv.x = __float2bfloat16(v2 - __bfloat162float(hv.x));
        lv.y = __float2bfloat16(v3 - __bfloat162float(hv.y));
        *(__nv_bfloat162*)(g_AOh + base1 + d) = hv;
        *(__nv_bfloat162*)(g_AOl + base1 + d) = lv;
    }
}

// ---- launcher ----
extern "C" void kernel_launch(void* const* d_in, const int* in_sizes, int n_in,
                              void* d_out, int out_size)
{
    const float* query = (const float*)d_in[0];
    const float *Wq=(const float*)d_in[1], *bq=(const float*)d_in[2];
    const float *Wk=(const float*)d_in[3], *bk=(const float*)d_in[4];
    const float *Wv=(const float*)d_in[5], *bv=(const float*)d_in[6];
    const float *Wo=(const float*)d_in[7], *bo=(const float*)d_in[8];
    const float *rel=(const float*)d_in[9];
    const float *gruW=(const float*)d_in[10], *grub=(const float*)d_in[11], *gruc=(const float*)d_in[12];

    cudaFuncSetAttribute(attn_mma, cudaFuncAttributeMaxDynamicSharedMemorySize, AS_TOTAL);

    bucket_kernel<<<dim3(4, SLEN), 256>>>();
    gate_kernel<<<BATCH*NH*SLEN/256, 256>>>(query, gruW, grub, gruc);
    split_x_kernel<<<MROWS*EMB/1024, 256>>>(query);
    trans_w_kernel<<<dim3(EMB/32, EMB/32, 4), 256>>>(Wq, Wk, Wv, Wo);
    gemm_qkv_mma<<<dim3(EMB/128, MROWS/128, 3), 256>>>(bq, bk, bv);
    attn_mma<<<dim3(BATCH*NH, SLEN/64), 128, AS_TOTAL>>>(rel);
    gemm_out_mma<<<dim3(EMB/128, MROWS/128), 256>>>(bo, (float*)d_out);
}

// round 6
// speedup vs baseline: 3.9063x; 1.6923x over previous
#include <cuda_runtime.h>
#include <cuda_fp16.h>
#include <cstdint>
#include <math.h>

#define BATCH 8
#define SLEN 1024
#define EMB 768
#define NH 12
#define HD 64
#define MROWS (BATCH*SLEN)

__device__ float g_gate[BATCH*NH*SLEN];
__device__ unsigned char g_bucket[SLEN*SLEN];
__device__ __half g_Xh[MROWS*EMB], g_Xl[MROWS*EMB];
__device__ __half g_AOh[MROWS*EMB], g_AOl[MROWS*EMB];
__device__ __half g_WTh[4*EMB*EMB];                    // W^T [n][k], hi only
__device__ __half g_Qh[BATCH*NH*SLEN*HD];              // single fp16
__device__ __half g_Kh[BATCH*NH*SLEN*HD];
__device__ __half g_Vh[BATCH*NH*SLEN*HD];

__device__ __forceinline__ uint32_t smem_u32(const void* p) {
    uint32_t a;
    asm("{.reg .u64 t; cvta.to.shared.u64 t,%1; cvt.u32.u64 %0,t;}" : "=r"(a) : "l"(p));
    return a;
}
__device__ __forceinline__ void ldm4(uint32_t* r, uint32_t addr) {
    asm volatile("ldmatrix.sync.aligned.m8n8.x4.shared.b16 {%0,%1,%2,%3}, [%4];"
        : "=r"(r[0]),"=r"(r[1]),"=r"(r[2]),"=r"(r[3]) : "r"(addr));
}
__device__ __forceinline__ void ldm4t(uint32_t* r, uint32_t addr) {
    asm volatile("ldmatrix.sync.aligned.m8n8.x4.trans.shared.b16 {%0,%1,%2,%3}, [%4];"
        : "=r"(r[0]),"=r"(r[1]),"=r"(r[2]),"=r"(r[3]) : "r"(addr));
}
__device__ __forceinline__ void mma16816(float* c, const uint32_t* a, const uint32_t* b) {
    asm volatile("mma.sync.aligned.m16n8k16.row.col.f32.f16.f16.f32 "
        "{%0,%1,%2,%3}, {%4,%5,%6,%7}, {%8,%9}, {%0,%1,%2,%3};"
        : "+f"(c[0]),"+f"(c[1]),"+f"(c[2]),"+f"(c[3])
        : "r"(a[0]),"r"(a[1]),"r"(a[2]),"r"(a[3]), "r"(b[0]),"r"(b[1]));
}
__device__ __forceinline__ uint32_t packh2(float hi, float lo) {
    uint32_t r;
    asm("cvt.rn.f16x2.f32 %0, %1, %2;" : "=r"(r) : "f"(hi), "f"(lo));
    return r;
}
__device__ __forceinline__ void cpa16(uint32_t saddr, const void* g) {
    asm volatile("cp.async.cg.shared.global [%0], [%1], 16;" :: "r"(saddr), "l"(g));
}
#define CP_COMMIT() asm volatile("cp.async.commit_group;" ::: "memory")
#define CP_WAIT0()  asm volatile("cp.async.wait_group 0;" ::: "memory")

// e^x for x<=0 on FMA pipe, max rel err ~2.4e-6
__device__ __forceinline__ float fexp(float x) {
    float y = fmaxf(x * 1.4426950408889634f, -80.f);
    float t = y + 12582912.f;
    int  i = __float_as_int(t) << 23;
    float f = y - (t - 12582912.f);
    float p = 0.0013333558f;
    p = fmaf(p, f, 0.0096181291f);
    p = fmaf(p, f, 0.0555041087f);
    p = fmaf(p, f, 0.2402265069f);
    p = fmaf(p, f, 0.6931471806f);
    p = fmaf(p, f, 1.0f);
    return __int_as_float(__float_as_int(p) + i);
}

// ---- bucket ----
__global__ __launch_bounds__(256) void bucket_kernel() {
    int k = blockIdx.x*256 + threadIdx.x, q = blockIdx.y;
    int rp = k - q, base = (rp>0)?16:0, a = abs(rp), add;
    if(a<8)add=a; else if(a<12)add=8; else if(a<16)add=9; else if(a<23)add=10;
    else if(a<32)add=11; else if(a<46)add=12; else if(a<64)add=13; else if(a<91)add=14; else add=15;
    g_bucket[q*SLEN+k] = (unsigned char)(base+add);
}

// ---- gate ----
__global__ __launch_bounds__(256) void gate_kernel(
    const float* __restrict__ query, const float* __restrict__ gW,
    const float* __restrict__ gb, const float* __restrict__ gc)
{
    __shared__ float sw0[64], sw1[64];
    int tid = threadIdx.x;
    if (tid < 64) {
        const float* w = gW + tid*8;
        sw0[tid] = w[0]+w[1]+w[2]+w[3];
        sw1[tid] = w[4]+w[5]+w[6]+w[7];
    }
    __syncthreads();
    float b0 = gb[0]+gb[1]+gb[2]+gb[3], b1 = gb[4]+gb[5]+gb[6]+gb[7];
    int idx = blockIdx.x*256 + tid;
    int s = idx & (SLEN-1), h = (idx>>10)%NH, b = idx/(NH*SLEN);
    const float* q = query + ((size_t)(b*SLEN+s))*EMB + h*HD;
    float z0 = b0, z1 = b1;
#pragma unroll 8
    for (int d = 0; d < HD; d++) { float v = __ldg(&q[d]); z0 += v*sw0[d]; z1 += v*sw1[d]; }
    float g0 = 1.f/(1.f+expf(-z0)), g1 = 1.f/(1.f+expf(-z1));
    g_gate[idx] = g0*(g1*gc[h]-1.f)+2.f;
}

// ---- prep: split X into fp16 hi/lo ----
__global__ __launch_bounds__(256) void split_x_kernel(const float* __restrict__ x) {
    size_t i = ((size_t)blockIdx.x*256 + threadIdx.x)*4;
    float4 v = *(const float4*)(x+i);
    float vv[4] = {v.x,v.y,v.z,v.w};
#pragma unroll
    for (int j = 0; j < 4; j++) {
        __half h = __float2half_rn(vv[j]);
        g_Xh[i+j] = h;
        g_Xl[i+j] = __float2half_rn(vv[j] - __half2float(h));
    }
}

// ---- prep: transpose W, hi fp16 only ----
__global__ __launch_bounds__(256) void trans_w_kernel(
    const float* __restrict__ wq, const float* __restrict__ wk,
    const float* __restrict__ wv, const float* __restrict__ wo)
{
    __shared__ float t[32][33];
    int z = blockIdx.z;
    const float* W = (z==0)?wq:(z==1)?wk:(z==2)?wv:wo;
    int tx = threadIdx.x & 31, ty = threadIdx.x >> 5;
    int n0 = blockIdx.x*32, k0 = blockIdx.y*32;
#pragma unroll
    for (int r = 0; r < 4; r++)
        t[ty+r*8][tx] = W[(size_t)(k0+ty+r*8)*EMB + n0+tx];
    __syncthreads();
#pragma unroll
    for (int r = 0; r < 4; r++) {
        size_t o = (size_t)z*EMB*EMB + (size_t)(n0+ty+r*8)*EMB + k0+tx;
        g_WTh[o] = __float2half_rn(t[tx][ty+r*8]);
    }
}

// ==== fp16 2-term GEMM: block 128x128, 4 warps of 32(M)x128(N) ====
// smem: per stage 3 tiles (Ah, Al, Bh) of [128][40] fp16 (80B pitch).
#define GTB 10240
#define GSTAGE (3*GTB)
#define G_SMEM (2*GSTAGE)

__device__ __forceinline__ void cpa_tile(const __half* __restrict__ g,
                                         int row0, int kc, uint32_t sdst, int tid) {
#pragma unroll
    for (int r = 0; r < 4; r++) {
        int u = tid + r*128, row = u >> 2, co = u & 3;
        cpa16(sdst + row*80 + co*16, g + (size_t)(row0+row)*EMB + kc + co*8);
    }
}

__device__ __forceinline__ void gemm_core(
    const __half* Ah, const __half* Al, const __half* Bh,
    int bm, int bn, char* sm, float c[2][16][4])
{
    int tid = threadIdx.x, lane = tid & 31, wid = tid >> 5;
    uint32_t sb = smem_u32(sm);
    uint32_t aoff = (((lane>>3)&1)*8 + (lane&7))*80 + (lane>>4)*16;
    uint32_t boff = ((lane>>4)*8 + (lane&7))*80 + ((lane>>3)&1)*16;

    cpa_tile(Ah, bm, 0, sb, tid);
    cpa_tile(Al, bm, 0, sb + GTB, tid);
    cpa_tile(Bh, bn, 0, sb + 2*GTB, tid);
    CP_COMMIT();

    for (int cI = 0; cI < 24; cI++) {
        CP_WAIT0();
        __syncthreads();
        if (cI < 23) {
            uint32_t st = sb + ((cI+1)&1)*GSTAGE;
            int kc = (cI+1)*32;
            cpa_tile(Ah, bm, kc, st, tid);
            cpa_tile(Al, bm, kc, st + GTB, tid);
            cpa_tile(Bh, bn, kc, st + 2*GTB, tid);
            CP_COMMIT();
        }
        uint32_t st = sb + (cI&1)*GSTAGE;
        uint32_t aBh = st + wid*32*80 + aoff;
        uint32_t aBl = st + GTB + wid*32*80 + aoff;
        uint32_t bB  = st + 2*GTB + boff;
#pragma unroll
        for (int ks = 0; ks < 64; ks += 32) {   // bytes: k16 = 32B
            uint32_t ah[2][4], al[2][4];
#pragma unroll
            for (int mi = 0; mi < 2; mi++) {
                ldm4(ah[mi], aBh + mi*16*80 + ks);
                ldm4(al[mi], aBl + mi*16*80 + ks);
            }
#pragma unroll
            for (int jf = 0; jf < 8; jf++) {
                uint32_t rb[4];
                ldm4(rb, bB + jf*16*80 + ks);
#pragma unroll
                for (int mi = 0; mi < 2; mi++) {
                    mma16816(c[mi][jf*2],   ah[mi], rb);
                    mma16816(c[mi][jf*2],   al[mi], rb);
                    mma16816(c[mi][jf*2+1], ah[mi], rb+2);
                    mma16816(c[mi][jf*2+1], al[mi], rb+2);
                }
            }
        }
        __syncthreads();
    }
}

__global__ __launch_bounds__(128) void gemm_qkv_mma(
    const float* __restrict__ bq, const float* __restrict__ bk, const float* __restrict__ bv)
{
    extern __shared__ char sm[];
    int z = blockIdx.z, bm = blockIdx.y*128, bn = blockIdx.x*128;
    float c[2][16][4] = {};
    gemm_core(g_Xh, g_Xl, g_WTh + (size_t)z*EMB*EMB, bm, bn, sm, c);

    const float* bias = (z==0)?bq:(z==1)?bk:bv;
    __half* Out = (z==0)?g_Qh:(z==1)?g_Kh:g_Vh;
    float scale = (z==0)?0.125f:1.f;
    int lane = threadIdx.x & 31, wid = threadIdx.x >> 5;
    int g = lane >> 2, t2 = (lane & 3)*2;
#pragma unroll
    for (int mi = 0; mi < 2; mi++)
#pragma unroll
        for (int nf = 0; nf < 16; nf++) {
            int col = bn + nf*8 + t2;
            int h = col >> 6, d0 = col & 63;
            float bx = __ldg(&bias[col]), by = __ldg(&bias[col+1]);
#pragma unroll
            for (int rr = 0; rr < 2; rr++) {
                int m = bm + wid*32 + mi*16 + g + rr*8;
                int b = m >> 10, s = m & (SLEN-1);
                float vx = (c[mi][nf][rr*2+0] + bx)*scale;
                float vy = (c[mi][nf][rr*2+1] + by)*scale;
                __half2 hv;
                hv.x = __float2half_rn(vx); hv.y = __float2half_rn(vy);
                *(__half2*)(Out + ((size_t)(b*NH+h)*SLEN + s)*HD + d0) = hv;
            }
        }
}

__global__ __launch_bounds__(128) void gemm_out_mma(
    const float* __restrict__ bo, float* __restrict__ out)
{
    extern __shared__ char sm[];
    int bm = blockIdx.y*128, bn = blockIdx.x*128;
    float c[2][16][4] = {};
    gemm_core(g_AOh, g_AOl, g_WTh + (size_t)3*EMB*EMB, bm, bn, sm, c);

    int lane = threadIdx.x & 31, wid = threadIdx.x >> 5;
    int g = lane >> 2, t2 = (lane & 3)*2;
#pragma unroll
    for (int mi = 0; mi < 2; mi++)
#pragma unroll
        for (int nf = 0; nf < 16; nf++) {
            int col = bn + nf*8 + t2;
            float bx = __ldg(&bo[col]), by = __ldg(&bo[col+1]);
#pragma unroll
            for (int rr = 0; rr < 2; rr++) {
                int m = bm + wid*32 + mi*16 + g + rr*8;
                float2 v;
                v.x = c[mi][nf][rr*2+0] + bx;
                v.y = c[mi][nf][rr*2+1] + by;
                *(float2*)(out + (size_t)m*EMB + col) = v;
            }
        }
}

// ==== fp16 flash attention: q-tile 128, 4 warps of 32 q-rows ====
// smem: Qh [128][72] (18432B); K/V stages: (Kh 9216 + Vh 9216)*2; gate 512; relw 128
#define AP 72
#define AS_KV 18432
#define KVST 18432
#define AS_GATE (18432 + 2*KVST)
#define AS_RELW (AS_GATE + 512)
#define AS_TOTAL (AS_RELW + 128)

__global__ __launch_bounds__(128) void attn_mma(const float* __restrict__ rel_embed)
{
    extern __shared__ char smc[];
    __half* qs = (__half*)smc;
    float* gate_s = (float*)(smc + AS_GATE);
    float* relw   = (float*)(smc + AS_RELW);

    int bh = blockIdx.x, qb = blockIdx.y, h = bh % NH;
    int tid = threadIdx.x, lane = tid & 31, w = tid >> 5;
    int g = lane >> 2, t2 = (lane & 3)*2;

    const __half* Qg = g_Qh + ((size_t)bh*SLEN + qb*128)*HD;
    const __half* Kg = g_Kh + (size_t)bh*SLEN*HD;
    const __half* Vg = g_Vh + (size_t)bh*SLEN*HD;

    // issue K/V tile 0
    {
        uint32_t kd = smem_u32(smc + AS_KV);
#pragma unroll
        for (int r = 0; r < 4; r++) {
            int u = tid + r*128, row = u >> 3, co = u & 7;
            cpa16(kd + row*144 + co*16,        Kg + (size_t)row*HD + co*8);
            cpa16(kd + 9216 + row*144 + co*16, Vg + (size_t)row*HD + co*8);
        }
        CP_COMMIT();
    }
    // Q to smem
#pragma unroll
    for (int r = 0; r < 8; r++) {
        int u = tid + r*128, row = u >> 3, co = u & 7;
        *(uint4*)(qs + row*AP + co*8) = *(const uint4*)(Qg + row*HD + co*8);
    }
    gate_s[tid] = g_gate[bh*SLEN + qb*128 + tid];
    if (tid < 32) relw[tid] = rel_embed[tid*NH + h];
    __syncthreads();

    uint32_t aoff = (((lane>>3)&1)*8 + (lane&7))*144 + (lane>>4)*16;
    uint32_t boff = ((lane>>4)*8 + (lane&7))*144 + ((lane>>3)&1)*16;

    // Q fragments (held in regs for the whole loop)
    uint32_t qf[2][4][4];
    {
        uint32_t qB = smem_u32(qs) + w*32*144 + aoff;
#pragma unroll
        for (int mi = 0; mi < 2; mi++)
#pragma unroll
            for (int ks = 0; ks < 4; ks++)
                ldm4(qf[mi][ks], qB + mi*16*144 + ks*32);
    }
    float gq[2][2];
    const unsigned char* br[2][2];
    int q0 = qb*128 + w*32 + g;
#pragma unroll
    for (int mi = 0; mi < 2; mi++) {
        gq[mi][0] = gate_s[w*32 + mi*16 + g];
        gq[mi][1] = gate_s[w*32 + mi*16 + g + 8];
        br[mi][0] = g_bucket + (size_t)(q0 + mi*16)*SLEN;
        br[mi][1] = br[mi][0] + 8*SLEN;
    }

    float o[2][8][4] = {};
    float m[2][2] = {{-1e30f,-1e30f},{-1e30f,-1e30f}};
    float l[2][2] = {};

    for (int kb = 0; kb < 16; kb++) {
        CP_WAIT0();
        __syncthreads();
        if (kb < 15) {
            uint32_t kd = smem_u32(smc + AS_KV + ((kb+1)&1)*KVST);
#pragma unroll
            for (int r = 0; r < 4; r++) {
                int u = tid + r*128, row = u >> 3, co = u & 7;
                size_t go = (size_t)((kb+1)*64 + row)*HD + co*8;
                cpa16(kd + row*144 + co*16,        Kg + go);
                cpa16(kd + 9216 + row*144 + co*16, Vg + go);
            }
            CP_COMMIT();
        }
        uint32_t kB = smem_u32(smc + AS_KV + (kb&1)*KVST) + boff;
        uint32_t vB = smem_u32(smc + AS_KV + (kb&1)*KVST + 9216) + aoff;

        // ---- S = Q K^T (single fp16) ----
        float s[2][8][4] = {};
#pragma unroll
        for (int ks = 0; ks < 4; ks++)
#pragma unroll
            for (int nb = 0; nb < 4; nb++) {
                uint32_t rk[4];
                ldm4(rk, kB + nb*16*144 + ks*32);
#pragma unroll
                for (int mi = 0; mi < 2; mi++) {
                    mma16816(s[mi][nb*2],   qf[mi][ks], rk);
                    mma16816(s[mi][nb*2+1], qf[mi][ks], rk+2);
                }
            }

        // ---- bias: gate * rel_pos ----
        int c0 = kb*64 + t2;
#pragma unroll
        for (int mi = 0; mi < 2; mi++)
#pragma unroll
            for (int nf = 0; nf < 8; nf++) {
                int cc = c0 + nf*8;
                s[mi][nf][0] += gq[mi][0]*relw[__ldg(&br[mi][0][cc])];
                s[mi][nf][1] += gq[mi][0]*relw[__ldg(&br[mi][0][cc+1])];
                s[mi][nf][2] += gq[mi][1]*relw[__ldg(&br[mi][1][cc])];
                s[mi][nf][3] += gq[mi][1]*relw[__ldg(&br[mi][1][cc+1])];
            }

        // ---- online softmax ----
#pragma unroll
        for (int mi = 0; mi < 2; mi++) {
            float mx0 = -1e30f, mx1 = -1e30f;
#pragma unroll
            for (int nf = 0; nf < 8; nf++) {
                mx0 = fmaxf(mx0, fmaxf(s[mi][nf][0], s[mi][nf][1]));
                mx1 = fmaxf(mx1, fmaxf(s[mi][nf][2], s[mi][nf][3]));
            }
            mx0 = fmaxf(mx0, __shfl_xor_sync(~0u, mx0, 1));
            mx0 = fmaxf(mx0, __shfl_xor_sync(~0u, mx0, 2));
            mx1 = fmaxf(mx1, __shfl_xor_sync(~0u, mx1, 1));
            mx1 = fmaxf(mx1, __shfl_xor_sync(~0u, mx1, 2));
            float mn0 = fmaxf(m[mi][0], mx0), mn1 = fmaxf(m[mi][1], mx1);
            float a0 = fexp(m[mi][0]-mn0), a1 = fexp(m[mi][1]-mn1);
            float rs0 = 0.f, rs1 = 0.f;
#pragma unroll
            for (int nf = 0; nf < 8; nf++) {
                s[mi][nf][0] = fexp(s[mi][nf][0]-mn0); rs0 += s[mi][nf][0];
                s[mi][nf][1] = fexp(s[mi][nf][1]-mn0); rs0 += s[mi][nf][1];
                s[mi][nf][2] = fexp(s[mi][nf][2]-mn1); rs1 += s[mi][nf][2];
                s[mi][nf][3] = fexp(s[mi][nf][3]-mn1); rs1 += s[mi][nf][3];
            }
            rs0 += __shfl_xor_sync(~0u, rs0, 1); rs0 += __shfl_xor_sync(~0u, rs0, 2);
            rs1 += __shfl_xor_sync(~0u, rs1, 1); rs1 += __shfl_xor_sync(~0u, rs1, 2);
            l[mi][0] = l[mi][0]*a0 + rs0; l[mi][1] = l[mi][1]*a1 + rs1;
            m[mi][0] = mn0; m[mi][1] = mn1;
#pragma unroll
            for (int nf = 0; nf < 8; nf++) {
                o[mi][nf][0] *= a0; o[mi][nf][1] *= a0;
                o[mi][nf][2] *= a1; o[mi][nf][3] *= a1;
            }
        }

        // ---- O += P V  (Ph*V + Pl*V, V single fp16) ----
#pragma unroll
        for (int ks = 0; ks < 4; ks++) {
            uint32_t pah[2][4], pal[2][4];
#pragma unroll
            for (int mi = 0; mi < 2; mi++) {
                float* p0 = s[mi][2*ks];
                float* p1 = s[mi][2*ks+1];
                pah[mi][0] = packh2(p0[1], p0[0]);
                pah[mi][1] = packh2(p0[3], p0[2]);
                pah[mi][2] = packh2(p1[1], p1[0]);
                pah[mi][3] = packh2(p1[3], p1[2]);
#pragma unroll
                for (int q = 0; q < 4; q++) {
                    __half2 hh = *(__half2*)&pah[mi][q];
                    float* pp = (q < 2) ? p0 : p1;
                    int e = (q & 1)*2;
                    pal[mi][q] = packh2(pp[e+1] - __high2float(hh),
                                        pp[e]   - __low2float(hh));
                }
            }
#pragma unroll
            for (int db = 0; db < 4; db++) {
                uint32_t rv[4];
                ldm4t(rv, vB + ks*16*144 + db*32);
#pragma unroll
                for (int mi = 0; mi < 2; mi++) {
                    mma16816(o[mi][db*2],   pah[mi], rv);
                    mma16816(o[mi][db*2],   pal[mi], rv);
                    mma16816(o[mi][db*2+1], pah[mi], rv+2);
                    mma16816(o[mi][db*2+1], pal[mi], rv+2);
                }
            }
        }
    }

    // ---- epilogue: O/l -> AOh/AOl fp16 hi/lo at [b, s, h*64+d] ----
    int b = bh / NH;
#pragma unroll
    for (int mi = 0; mi < 2; mi++) {
        float inv0 = 1.f/l[mi][0], inv1 = 1.f/l[mi][1];
        int r0 = q0 + mi*16;
        size_t base0 = ((size_t)(b*SLEN) + r0)*EMB + h*HD;
        size_t base1 = base0 + (size_t)8*EMB;
#pragma unroll
        for (int nf = 0; nf < 8; nf++) {
            int d = nf*8 + t2;
            float v0 = o[mi][nf][0]*inv0, v1 = o[mi][nf][1]*inv0;
            float v2 = o[mi][nf][2]*inv1, v3 = o[mi][nf][3]*inv1;
            __half2 hv, lv;
            hv.x = __float2half_rn(v0); hv.y = __float2half_rn(v1);
            lv.x = __float2half_rn(v0 - __half2float(hv.x));
            lv.y = __float2half_rn(v1 - __half2float(hv.y));
            *(__half2*)(g_AOh + base0 + d) = hv;
            *(__half2*)(g_AOl + base0 + d) = lv;
            hv.x = __float2half_rn(v2); hv.y = __float2half_rn(v3);
            lv.x = __float2half_rn(v2 - __half2float(hv.x));
            lv.y = __float2half_rn(v3 - __half2float(hv.y));
            *(__half2*)(g_AOh + base1 + d) = hv;
            *(__half2*)(g_AOl + base1 + d) = lv;
        }
    }
}

// ---- launcher ----
extern "C" void kernel_launch(void* const* d_in, const int* in_sizes, int n_in,
                              void* d_out, int out_size)
{
    const float* query = (const float*)d_in[0];
    const float *Wq=(const float*)d_in[1], *bq=(const float*)d_in[2];
    const float *Wk=(const float*)d_in[3], *bk=(const float*)d_in[4];
    const float *Wv=(const float*)d_in[5], *bv=(const float*)d_in[6];
    const float *Wo=(const float*)d_in[7], *bo=(const float*)d_in[8];
    const float *rel=(const float*)d_in[9];
    const float *gruW=(const float*)d_in[10], *grub=(const float*)d_in[11], *gruc=(const float*)d_in[12];

    cudaFuncSetAttribute(attn_mma, cudaFuncAttributeMaxDynamicSharedMemorySize, AS_TOTAL);
    cudaFuncSetAttribute(gemm_qkv_mma, cudaFuncAttributeMaxDynamicSharedMemorySize, G_SMEM);
    cudaFuncSetAttribute(gemm_out_mma, cudaFuncAttributeMaxDynamicSharedMemorySize, G_SMEM);

    bucket_kernel<<<dim3(4, SLEN), 256>>>();
    gate_kernel<<<BATCH*NH*SLEN/256, 256>>>(query, gruW, grub, gruc);
    split_x_kernel<<<MROWS*EMB/1024, 256>>>(query);
    trans_w_kernel<<<dim3(EMB/32, EMB/32, 4), 256>>>(Wq, Wk, Wv, Wo);
    gemm_qkv_mma<<<dim3(EMB/128, MROWS/128, 3), 128, G_SMEM>>>(bq, bk, bv);
    attn_mma<<<dim3(BATCH*NH, SLEN/128), 128, AS_TOTAL>>>(rel);
    gemm_out_mma<<<dim3(EMB/128, MROWS/128), 128, G_SMEM>>>(bo, (float*)d_out);
}